// round 10
// baseline (speedup 1.0000x reference)
#include <cuda_runtime.h>

// ProjectLoss — FINAL (converged at memory roofline).
//
// B=2, H=W=64. grid_dist_tensor: [64,64,64,64] -> 4096 tiles x 4096 floats.
//
// Algebraic collapse: all per-(b,h,w) multipliers (gt, pred, gt_th, pred_mask)
// are non-negative scalars w.r.t. the (i,j) min axes, so
//   min_{ij}(s * dist_{ij}) = s * min_{ij}(dist_{ij}),
// reducing the [B,H,W,64,64] broadcast to ONE min per (h,w) tile.
//
// Traffic floor: read grid exactly once per call = 64 MB. Best measured
// 9.28 us = ~6.9 TB/s = the chip-wide LTS throughput cap (path-independent:
// LDG == TMA == LDG.cv), i.e. ~100% of the achievable roofline. Identical
// source measured 9.28 / 9.376 / 9.44 / 10.176 us across runs (+/-0.8 us
// harness noise); the lower edge is the true kernel time.
//
// Design: one warp per tile, barrier-free, no smem. Each warp streams its
// 16 KB tile as 4 rounds of 8 front-batched LDG.128 (4 KB in flight/warp),
// shuffle min-reduce, lanes 0/1 emit the three outputs for batches 0/1.
// 4096 warps = 512 blocks x 256 threads.

#define EPS_F   1e-8f
#define BIG_F   1000000.0f
#define HW      4096
#define BHW     8192

__global__ __launch_bounds__(256, 4)
void project_loss_kernel(const float* __restrict__ preds,
                         const float* __restrict__ gts,
                         const float* __restrict__ grid,
                         float* __restrict__ out)
{
    const int warp = (blockIdx.x * blockDim.x + threadIdx.x) >> 5; // 0..4095
    const int lane = threadIdx.x & 31;
    const int tile = warp;                 // one tile per warp

    // Each LDG.128 warp-instruction covers 512 contiguous bytes (coalesced).
    const float4* g4 = reinterpret_cast<const float4*>(grid + (size_t)tile * HW) + lane;

    float m = __int_as_float(0x7f800000);  // +inf

    // 4 rounds of 8 front-batched LDG.128 (4KB in flight per warp per round)
    #pragma unroll
    for (int r = 0; r < 4; r++) {
        float4 v0 = __ldg(g4 + (r * 8 + 0) * 32);
        float4 v1 = __ldg(g4 + (r * 8 + 1) * 32);
        float4 v2 = __ldg(g4 + (r * 8 + 2) * 32);
        float4 v3 = __ldg(g4 + (r * 8 + 3) * 32);
        float4 v4 = __ldg(g4 + (r * 8 + 4) * 32);
        float4 v5 = __ldg(g4 + (r * 8 + 5) * 32);
        float4 v6 = __ldg(g4 + (r * 8 + 6) * 32);
        float4 v7 = __ldg(g4 + (r * 8 + 7) * 32);

        float m0 = fminf(fminf(v0.x, v0.y), fminf(v0.z, v0.w));
        float m1 = fminf(fminf(v1.x, v1.y), fminf(v1.z, v1.w));
        float m2 = fminf(fminf(v2.x, v2.y), fminf(v2.z, v2.w));
        float m3 = fminf(fminf(v3.x, v3.y), fminf(v3.z, v3.w));
        float m4 = fminf(fminf(v4.x, v4.y), fminf(v4.z, v4.w));
        float m5 = fminf(fminf(v5.x, v5.y), fminf(v5.z, v5.w));
        float m6 = fminf(fminf(v6.x, v6.y), fminf(v6.z, v6.w));
        float m7 = fminf(fminf(v7.x, v7.y), fminf(v7.z, v7.w));

        m = fminf(m, fminf(fminf(fminf(m0, m1), fminf(m2, m3)),
                           fminf(fminf(m4, m5), fminf(m6, m7))));
    }

    // warp shuffle min-reduce
    #pragma unroll
    for (int o = 16; o > 0; o >>= 1)
        m = fminf(m, __shfl_xor_sync(0xFFFFFFFFu, m, o));

    // lanes 0 and 1 handle batch b = lane
    if (lane < 2) {
        const float dist = m + 1.0f;      // min(grid+1) == min(grid)+1
        const int b   = lane;
        const int idx = b * HW + tile;

        const float p = preds[idx];
        const float g = gts[idx];

        const float loss = -g * logf(p + EPS_F)
                           - (1.0f - g) * logf(fabsf(1.0f - p - EPS_F));

        const float pred_mask = p + (1.0f - p) * BIG_F;
        const float gt_th     = g + (1.0f - g) * BIG_F;

        out[idx]           = loss;
        out[BHW + idx]     = gt_th * dist * p;
        out[2 * BHW + idx] = g * dist * pred_mask;
    }
}

extern "C" void kernel_launch(void* const* d_in, const int* in_sizes, int n_in,
                              void* d_out, int out_size)
{
    const float* preds = (const float*)d_in[0];
    const float* gts   = (const float*)d_in[1];
    const float* grid  = (const float*)d_in[2];
    float* out = (float*)d_out;

    // 4096 warps = 512 blocks x 256 threads (8 warps/block), one tile per warp
    project_loss_kernel<<<512, 256>>>(preds, gts, grid, out);
}

// round 11
// speedup vs baseline: 1.0174x; 1.0174x over previous
#include <cuda_runtime.h>

// ProjectLoss — FINAL (converged at memory roofline).
//
// B=2, H=W=64. grid_dist_tensor: [64,64,64,64] -> 4096 tiles x 4096 floats.
//
// Algebraic collapse: all per-(b,h,w) multipliers (gt, pred, gt_th, pred_mask)
// are non-negative scalars w.r.t. the (i,j) min axes, so
//   min_{ij}(s * dist_{ij}) = s * min_{ij}(dist_{ij}),
// reducing the [B,H,W,64,64] broadcast to ONE min per (h,w) tile.
//
// Traffic floor: read grid exactly once per call = 64 MB. Identical source
// measured 9.28 / 9.376 / 9.376 / 9.44 / 10.176 us across five runs:
// modal ~9.38 us = ~6.9 TB/s = the chip-wide LTS throughput cap
// (path-independent: LDG == TMA == LDG.cv) -> ~100% of achievable roofline.
//
// Design: one warp per tile, barrier-free, no smem. Each warp streams its
// 16 KB tile as 4 rounds of 8 front-batched LDG.128 (4 KB in flight/warp),
// shuffle min-reduce, lanes 0/1 emit the three outputs for batches 0/1.
// 4096 warps = 512 blocks x 256 threads.

#define EPS_F   1e-8f
#define BIG_F   1000000.0f
#define HW      4096
#define BHW     8192

__global__ __launch_bounds__(256, 4)
void project_loss_kernel(const float* __restrict__ preds,
                         const float* __restrict__ gts,
                         const float* __restrict__ grid,
                         float* __restrict__ out)
{
    const int warp = (blockIdx.x * blockDim.x + threadIdx.x) >> 5; // 0..4095
    const int lane = threadIdx.x & 31;
    const int tile = warp;                 // one tile per warp

    // Each LDG.128 warp-instruction covers 512 contiguous bytes (coalesced).
    const float4* g4 = reinterpret_cast<const float4*>(grid + (size_t)tile * HW) + lane;

    float m = __int_as_float(0x7f800000);  // +inf

    // 4 rounds of 8 front-batched LDG.128 (4KB in flight per warp per round)
    #pragma unroll
    for (int r = 0; r < 4; r++) {
        float4 v0 = __ldg(g4 + (r * 8 + 0) * 32);
        float4 v1 = __ldg(g4 + (r * 8 + 1) * 32);
        float4 v2 = __ldg(g4 + (r * 8 + 2) * 32);
        float4 v3 = __ldg(g4 + (r * 8 + 3) * 32);
        float4 v4 = __ldg(g4 + (r * 8 + 4) * 32);
        float4 v5 = __ldg(g4 + (r * 8 + 5) * 32);
        float4 v6 = __ldg(g4 + (r * 8 + 6) * 32);
        float4 v7 = __ldg(g4 + (r * 8 + 7) * 32);

        float m0 = fminf(fminf(v0.x, v0.y), fminf(v0.z, v0.w));
        float m1 = fminf(fminf(v1.x, v1.y), fminf(v1.z, v1.w));
        float m2 = fminf(fminf(v2.x, v2.y), fminf(v2.z, v2.w));
        float m3 = fminf(fminf(v3.x, v3.y), fminf(v3.z, v3.w));
        float m4 = fminf(fminf(v4.x, v4.y), fminf(v4.z, v4.w));
        float m5 = fminf(fminf(v5.x, v5.y), fminf(v5.z, v5.w));
        float m6 = fminf(fminf(v6.x, v6.y), fminf(v6.z, v6.w));
        float m7 = fminf(fminf(v7.x, v7.y), fminf(v7.z, v7.w));

        m = fminf(m, fminf(fminf(fminf(m0, m1), fminf(m2, m3)),
                           fminf(fminf(m4, m5), fminf(m6, m7))));
    }

    // warp shuffle min-reduce
    #pragma unroll
    for (int o = 16; o > 0; o >>= 1)
        m = fminf(m, __shfl_xor_sync(0xFFFFFFFFu, m, o));

    // lanes 0 and 1 handle batch b = lane
    if (lane < 2) {
        const float dist = m + 1.0f;      // min(grid+1) == min(grid)+1
        const int b   = lane;
        const int idx = b * HW + tile;

        const float p = preds[idx];
        const float g = gts[idx];

        const float loss = -g * logf(p + EPS_F)
                           - (1.0f - g) * logf(fabsf(1.0f - p - EPS_F));

        const float pred_mask = p + (1.0f - p) * BIG_F;
        const float gt_th     = g + (1.0f - g) * BIG_F;

        out[idx]           = loss;
        out[BHW + idx]     = gt_th * dist * p;
        out[2 * BHW + idx] = g * dist * pred_mask;
    }
}

extern "C" void kernel_launch(void* const* d_in, const int* in_sizes, int n_in,
                              void* d_out, int out_size)
{
    const float* preds = (const float*)d_in[0];
    const float* gts   = (const float*)d_in[1];
    const float* grid  = (const float*)d_in[2];
    float* out = (float*)d_out;

    // 4096 warps = 512 blocks x 256 threads (8 warps/block), one tile per warp
    project_loss_kernel<<<512, 256>>>(preds, gts, grid, out);
}